// round 12
// baseline (speedup 1.0000x reference)
#include <cuda_runtime.h>
#include <cstdint>

#define E_NUM 60000
#define LDX   3712          // 29 * 128, row stride of x and out

// scratch (static device globals: allowed)
__device__ float g_xr[(long long)E_NUM * LDX];   // rna-rounded x
__device__ float g_w0[896 * 896];                // rna-rounded weights, [k][n]
__device__ float g_w1[1536 * 1536];
__device__ float g_w2[1280 * 1280];

__device__ __forceinline__ float to_tf32(float x) {
    uint32_t u;
    asm("cvt.rna.tf32.f32 %0, %1;" : "=r"(u) : "f"(x));
    return __uint_as_float(u);
}
__device__ __forceinline__ uint32_t s2u(const void* p) {
    uint32_t a;
    asm("{ .reg .u64 t; cvta.to.shared.u64 t, %1; cvt.u32.u64 %0, t; }" : "=r"(a) : "l"(p));
    return a;
}

// ---------------- prep passes ----------------

__global__ void prep_round_k(const float* __restrict__ x) {
    long long i = (long long)blockIdx.x * blockDim.x + threadIdx.x;
    const long long n4 = (long long)E_NUM * LDX / 4;
    if (i < n4) {
        float4 v = reinterpret_cast<const float4*>(x)[i];
        v.x = to_tf32(v.x); v.y = to_tf32(v.y);
        v.z = to_tf32(v.z); v.w = to_tf32(v.w);
        reinterpret_cast<float4*>(g_xr)[i] = v;
    }
}
__global__ void prep_copy_k(const float* __restrict__ src, int n) {
    int i = blockIdx.x * blockDim.x + threadIdx.x;
    if (i < n) g_w0[i] = to_tf32(src[i]);
}
// W' = [[Wa, Wb], [-Wb, Wa]] (2H x 2H) from src (H x 2H), rna-rounded.
__global__ void prep_so2_k(const float* __restrict__ src, int H, int which) {
    float* dst = (which == 1) ? g_w1 : g_w2;
    const int W2 = 2 * H;
    int i = blockIdx.x * blockDim.x + threadIdx.x;
    if (i >= W2 * W2) return;
    int k = i / W2;
    int n = i - k * W2;
    float v;
    if (k < H) {
        v = src[k * W2 + n];
    } else {
        int kk = k - H;
        v = (n < H) ? -src[kk * W2 + n + H] : src[kk * W2 + n - H];
    }
    dst[i] = to_tf32(v);
}

// ---------------- GEMM: C = A(ExK, ld LDX) * W(KxN) (+bias) ----------------
// Block tile 128x128x32, 128 threads (4 warps), warp grid 2x2, warp tile 64x64.
// 2 CTAs/SM. A and B both pre-rounded in gmem -> pure cp.async 3-stage
// pipeline; mainloop is cp.async issue + fragment LDS + MMA only.
// AS_STRIDE 36 / BS_STRIDE 136 keep all fragment loads conflict-free.

#define AS_STRIDE 36
#define BS_STRIDE 136
#define AS_BUF (128 * AS_STRIDE)    // 4608 floats / stage
#define BS_BUF (32 * BS_STRIDE)     // 4352 floats / stage
#define S_NUM 3
#define SMEM_BYTES (S_NUM * (AS_BUF + BS_BUF) * 4)   // 107520

__global__ __launch_bounds__(128, 2) void gemm_tf32_k(
    const float* __restrict__ A, const float* __restrict__ Bw,
    const float* __restrict__ bias, float* __restrict__ C,
    int N, int K)
{
    extern __shared__ float smem[];
    float* As = smem;                      // [3][128][36]
    float* Bs = smem + S_NUM * AS_BUF;     // [3][32][136]

    const int tid  = threadIdx.x;
    const int lane = tid & 31;
    const int warp = tid >> 5;         // 0..3
    const int wm   = warp >> 1;        // 0..1  (64-row strip)
    const int wn   = warp & 1;         // 0..1  (64-col strip)
    const int bn   = blockIdx.x;       // fastest: A tile L2-reused across N strip
    const int bm   = blockIdx.y;

    const int lr = lane >> 2;          // 0..7
    const int lc = lane & 3;           // 0..3

    float acc[4][8][4];
#pragma unroll
    for (int a = 0; a < 4; a++)
#pragma unroll
        for (int b = 0; b < 8; b++)
#pragma unroll
            for (int c = 0; c < 4; c++) acc[a][b][c] = 0.f;

    const int ktiles = K >> 5;

    // Per-tile: A = 128 rows x 128B = 1024 x16B chunks, B likewise; 8+8 per thread.
    auto load_tile = [&](int kt, int slot) {
        float* a = As + slot * AS_BUF;
        float* b = Bs + slot * BS_BUF;
#pragma unroll
        for (int i = 0; i < 8; i++) {
            int c = tid + i * 128;
            int r = c >> 3, sub = c & 7;
            int m = bm * 128 + r;
            int pb = (m < E_NUM) ? 16 : 0;
            if (m >= E_NUM) m = E_NUM - 1;      // keep address valid; pb=0 zero-fills
            uint32_t dst = s2u(a + r * AS_STRIDE + sub * 4);
            const float* src = A + (size_t)m * LDX + kt * 32 + sub * 4;
            asm volatile("cp.async.cg.shared.global [%0], [%1], 16, %2;"
                         :: "r"(dst), "l"(src), "r"(pb) : "memory");
        }
#pragma unroll
        for (int i = 0; i < 8; i++) {
            int c = tid + i * 128;
            int r = c >> 5, sub = c & 31;
            uint32_t dst = s2u(b + r * BS_STRIDE + sub * 4);
            const float* src = Bw + (size_t)(kt * 32 + r) * N + bn * 128 + sub * 4;
            asm volatile("cp.async.cg.shared.global [%0], [%1], 16;"
                         :: "r"(dst), "l"(src) : "memory");
        }
        asm volatile("cp.async.commit_group;" ::: "memory");
    };

    auto compute_ks = [&](int slot, int ks) {
        const float* a = As + slot * AS_BUF;
        const float* b = Bs + slot * BS_BUF;
        const int k0 = ks * 8;
        uint32_t af[4][4];
#pragma unroll
        for (int im = 0; im < 4; im++) {
            int r  = wm * 64 + im * 16 + lr;
            int kc = k0 + lc;
            af[im][0] = __float_as_uint(a[r * AS_STRIDE + kc]);
            af[im][1] = __float_as_uint(a[(r + 8) * AS_STRIDE + kc]);
            af[im][2] = __float_as_uint(a[r * AS_STRIDE + kc + 4]);
            af[im][3] = __float_as_uint(a[(r + 8) * AS_STRIDE + kc + 4]);
        }
        uint32_t bf[8][2];
#pragma unroll
        for (int jn = 0; jn < 8; jn++) {
            int cn = wn * 64 + jn * 8 + lr;
            bf[jn][0] = __float_as_uint(b[(k0 + lc) * BS_STRIDE + cn]);
            bf[jn][1] = __float_as_uint(b[(k0 + 4 + lc) * BS_STRIDE + cn]);
        }
#pragma unroll
        for (int im = 0; im < 4; im++)
#pragma unroll
            for (int jn = 0; jn < 8; jn++) {
                asm volatile(
                    "mma.sync.aligned.m16n8k8.row.col.f32.tf32.tf32.f32 "
                    "{%0,%1,%2,%3}, {%4,%5,%6,%7}, {%8,%9}, {%0,%1,%2,%3};\n"
                    : "+f"(acc[im][jn][0]), "+f"(acc[im][jn][1]),
                      "+f"(acc[im][jn][2]), "+f"(acc[im][jn][3])
                    : "r"(af[im][0]), "r"(af[im][1]),
                      "r"(af[im][2]), "r"(af[im][3]),
                      "r"(bf[jn][0]), "r"(bf[jn][1]));
            }
    };

    // prologue: stages 0 and 1 in flight
    load_tile(0, 0);
    if (ktiles > 1) load_tile(1, 1);

    int slot = 0;
    for (int kt = 0; kt < ktiles; kt++) {
        if (kt + 1 < ktiles)
            asm volatile("cp.async.wait_group 1;" ::: "memory");
        else
            asm volatile("cp.async.wait_group 0;" ::: "memory");
        __syncthreads();   // tile kt visible to all; slot (kt-1)%3 free for reuse
        if (kt + 2 < ktiles) {
            int s2 = kt + 2 - 3 * ((kt + 2) / 3);
            load_tile(kt + 2, s2);
        }
        compute_ks(slot, 0);
        compute_ks(slot, 1);
        compute_ks(slot, 2);
        compute_ks(slot, 3);
        slot++; if (slot == S_NUM) slot = 0;
    }

    // epilogue
#pragma unroll
    for (int im = 0; im < 4; im++) {
        int r0 = bm * 128 + wm * 64 + im * 16 + lr;
#pragma unroll
        for (int jn = 0; jn < 8; jn++) {
            int cg = bn * 128 + wn * 64 + jn * 8 + lc * 2;
            float bv0 = 0.f, bv1 = 0.f;
            if (bias) { bv0 = bias[cg]; bv1 = bias[cg + 1]; }
            if (r0 < E_NUM) {
                float2 v; v.x = acc[im][jn][0] + bv0; v.y = acc[im][jn][1] + bv1;
                *reinterpret_cast<float2*>(C + (size_t)r0 * LDX + cg) = v;
            }
            if (r0 + 8 < E_NUM) {
                float2 v; v.x = acc[im][jn][2] + bv0; v.y = acc[im][jn][3] + bv1;
                *reinterpret_cast<float2*>(C + (size_t)(r0 + 8) * LDX + cg) = v;
            }
        }
    }
}

// ---------------- launch ----------------

extern "C" void kernel_launch(void* const* d_in, const int* in_sizes, int n_in,
                              void* d_out, int out_size)
{
    const float* x  = (const float*)d_in[0];
    // d_in[1] = x_edge: unused by the reference
    const float* w0 = (const float*)d_in[2];
    const float* b0 = (const float*)d_in[3];
    const float* w1 = (const float*)d_in[4];
    const float* w2 = (const float*)d_in[5];
    float* out = (float*)d_out;

    const long long n4 = (long long)E_NUM * LDX / 4;   // 13,920,000
    prep_round_k<<<(int)((n4 + 255) / 256), 256>>>(x);
    prep_copy_k<<<(896 * 896 + 255) / 256, 256>>>(w0, 896 * 896);
    prep_so2_k<<<(1536 * 1536 + 255) / 256, 256>>>(w1, 768, 1);
    prep_so2_k<<<(1280 * 1280 + 255) / 256, 256>>>(w2, 640, 2);

    float *xr, *pw0, *pw1, *pw2;
    cudaGetSymbolAddress((void**)&xr,  g_xr);
    cudaGetSymbolAddress((void**)&pw0, g_w0);
    cudaGetSymbolAddress((void**)&pw1, g_w1);
    cudaGetSymbolAddress((void**)&pw2, g_w2);

    cudaFuncSetAttribute(gemm_tf32_k,
                         cudaFuncAttributeMaxDynamicSharedMemorySize, SMEM_BYTES);

    const int mb = (E_NUM + 127) / 128;   // 469
    // m=0: (E,896) @ (896,896) + bias  -> out cols 0..895
    gemm_tf32_k<<<dim3(7, mb), 128, SMEM_BYTES>>>(xr,        pw0, b0,      out,        896,  896);
    // m=1: (E,1536) @ (1536,1536)      -> out cols 896..2431
    gemm_tf32_k<<<dim3(12, mb), 128, SMEM_BYTES>>>(xr + 896,  pw1, nullptr, out + 896,  1536, 1536);
    // m=2: (E,1280) @ (1280,1280)      -> out cols 2432..3711
    gemm_tf32_k<<<dim3(10, mb), 128, SMEM_BYTES>>>(xr + 2432, pw2, nullptr, out + 2432, 1280, 1280);
}

// round 13
// speedup vs baseline: 1.2292x; 1.2292x over previous
#include <cuda_runtime.h>
#include <cstdint>

#define E_NUM 60000
#define LDX   3712          // 29 * 128, row stride of x and out

// rna-rounded weights, TRANSPOSED [n][k] (static device globals: allowed)
__device__ float g_w0t[896 * 896];
__device__ float g_w1t[1536 * 1536];
__device__ float g_w2t[1280 * 1280];

__device__ __forceinline__ float to_tf32(float x) {
    uint32_t u;
    asm("cvt.rna.tf32.f32 %0, %1;" : "=r"(u) : "f"(x));
    return __uint_as_float(u);
}
__device__ __forceinline__ uint32_t s2u(const void* p) {
    uint32_t a;
    asm("{ .reg .u64 t; cvta.to.shared.u64 t, %1; cvt.u32.u64 %0, t; }" : "=r"(a) : "l"(p));
    return a;
}

// ---------------- weight prep (rna-rounded, transposed to [n][k]) ----------------

__global__ void prep_w0t_k(const float* __restrict__ src) {
    int i = blockIdx.x * blockDim.x + threadIdx.x;   // dst-linear: [n][k]
    if (i >= 896 * 896) return;
    int n = i / 896, k = i - n * 896;
    g_w0t[i] = to_tf32(src[k * 896 + n]);
}
// W'^T where W' = [[Wa, Wb], [-Wb, Wa]], src = [Wa | Wb] (H x 2H).
// dst[n*2H + k] = W'[k][n], rna-rounded.
__global__ void prep_so2t_k(const float* __restrict__ src, int H, int which) {
    float* dst = (which == 1) ? g_w1t : g_w2t;
    const int W2 = 2 * H;
    int i = blockIdx.x * blockDim.x + threadIdx.x;
    if (i >= W2 * W2) return;
    int n = i / W2, k = i - n * W2;
    float v;
    if (k < H) {
        v = src[k * W2 + n];
    } else {
        int kk = k - H;
        v = (n < H) ? -src[kk * W2 + n + H] : src[kk * W2 + n - H];
    }
    dst[i] = to_tf32(v);
}

// ---------------- GEMM: C = A(ExK, ld LDX) * W(KxN) (+bias), W given as Wt[N][K] ----
// Block tile 128x128x32, 128 threads (4 warps), warp grid 2x2, warp tile 64x64.
// 2 CTAs/SM. A: LDG->rna->STS.128. B: LDG.128->STS.128 from transposed weights
// (Bt smem rows = 32 k-floats). All fragments loaded via ldmatrix.m8n8.x4
// (conflict-free with stride 36: phase bank index 9*row mod 8 is a permutation).

#define AS_STRIDE 36
#define AS_BUF (128 * AS_STRIDE)    // 4608 floats / stage (A)
#define BS_BUF (128 * AS_STRIDE)    // 4608 floats / stage (Bt)
#define SMEM_BYTES ((2 * AS_BUF + 2 * BS_BUF) * 4)   // 73728

__global__ __launch_bounds__(128, 2) void gemm_tf32_k(
    const float* __restrict__ A, const float* __restrict__ Bwt,
    const float* __restrict__ bias, float* __restrict__ C,
    int N, int K)
{
    extern __shared__ float smem[];
    float* As = smem;                  // [2][128 rows][36]  (row m, 32 k + pad)
    float* Bs = smem + 2 * AS_BUF;     // [2][128 rows][36]  (row n, 32 k + pad)

    const int tid  = threadIdx.x;
    const int lane = tid & 31;
    const int warp = tid >> 5;         // 0..3
    const int wm   = warp >> 1;        // 0..1  (64-row strip)
    const int wn   = warp & 1;         // 0..1  (64-col strip)
    const int bn   = blockIdx.x;       // fastest: A tile L2-reused across N strip
    const int bm   = blockIdx.y;

    const int lr = lane >> 2;          // 0..7
    const int lc = lane & 3;           // 0..3

    // ldmatrix lane-address offsets (floats), constant per thread:
    // A x4: m0 rows r0+row8 @k0 | m1 r0+8+row8 @k0 | m2 r0+row8 @k0+4 | m3 r0+8+row8 @k0+4
    // B x4: m0 n0+row8 @k0 | m1 n0+row8 @k0+4 | m2 n0+8+row8 @k0 | m3 n0+8+row8 @k0+4
    const int grp  = lane >> 3;        // 0..3
    const int row8 = lane & 7;
    const int aoff = (row8 + ((grp & 1) ? 8 : 0)) * AS_STRIDE + ((grp & 2) ? 4 : 0);
    const int boff = (row8 + ((grp & 2) ? 8 : 0)) * AS_STRIDE + ((grp & 1) ? 4 : 0);

    float acc[4][8][4];
#pragma unroll
    for (int a = 0; a < 4; a++)
#pragma unroll
        for (int b = 0; b < 8; b++)
#pragma unroll
            for (int c = 0; c < 4; c++) acc[a][b][c] = 0.f;

    const int ar   = tid >> 3;         // row base (0..15), rows ar + i*16
    const int asub = tid & 7;          // 16B sub-chunk

    const int ktiles = K >> 5;

    float4 aReg[8], bReg[4];

    auto ldgA = [&](int kt) {
#pragma unroll
        for (int i = 0; i < 8; i++) {
            int m = bm * 128 + ar + i * 16;
            if (m < E_NUM)
                aReg[i] = *reinterpret_cast<const float4*>(
                    A + (size_t)m * LDX + kt * 32 + asub * 4);
            else
                aReg[i] = make_float4(0.f, 0.f, 0.f, 0.f);
        }
    };
    // Bt tile: 128 n-rows x 32 k-floats = 1024 x16B chunks; halves of 4/thread.
    auto ldgB = [&](int kt, int h) {
#pragma unroll
        for (int i = 0; i < 4; i++) {
            int c = tid + (i + 4 * h) * 128;   // 0..1023
            int n = c >> 3, sub = c & 7;
            bReg[i] = *reinterpret_cast<const float4*>(
                Bwt + (size_t)(bn * 128 + n) * K + kt * 32 + sub * 4);
        }
    };
    auto stsA = [&](int buf) {
        float* a = As + buf * AS_BUF;
#pragma unroll
        for (int i = 0; i < 8; i++) {
            float4 v = aReg[i];
            v.x = to_tf32(v.x); v.y = to_tf32(v.y);
            v.z = to_tf32(v.z); v.w = to_tf32(v.w);
            *reinterpret_cast<float4*>(a + (ar + i * 16) * AS_STRIDE + asub * 4) = v;
        }
    };
    auto stsB = [&](int buf, int h) {
        float* b = Bs + buf * BS_BUF;
#pragma unroll
        for (int i = 0; i < 4; i++) {
            int c = tid + (i + 4 * h) * 128;
            int n = c >> 3, sub = c & 7;
            *reinterpret_cast<float4*>(b + n * AS_STRIDE + sub * 4) = bReg[i];
        }
    };

    auto compute_ks = [&](int buf, int ks) {
        const float* a  = As + buf * AS_BUF;
        const float* bt = Bs + buf * BS_BUF;
        const int k0 = ks * 8;
        uint32_t af[4][4], bf[8][2];
        const uint32_t a_u = s2u(a)  + (uint32_t)(aoff + k0) * 4u;
        const uint32_t b_u = s2u(bt) + (uint32_t)(boff + k0) * 4u;
#pragma unroll
        for (int im = 0; im < 4; im++) {
            uint32_t ad = a_u + (uint32_t)((wm * 64 + im * 16) * AS_STRIDE) * 4u;
            asm volatile(
                "ldmatrix.sync.aligned.m8n8.x4.shared.b16 {%0,%1,%2,%3}, [%4];"
                : "=r"(af[im][0]), "=r"(af[im][1]), "=r"(af[im][2]), "=r"(af[im][3])
                : "r"(ad));
        }
#pragma unroll
        for (int jp = 0; jp < 4; jp++) {
            uint32_t bd = b_u + (uint32_t)((wn * 64 + jp * 16) * AS_STRIDE) * 4u;
            asm volatile(
                "ldmatrix.sync.aligned.m8n8.x4.shared.b16 {%0,%1,%2,%3}, [%4];"
                : "=r"(bf[2 * jp][0]), "=r"(bf[2 * jp][1]),
                  "=r"(bf[2 * jp + 1][0]), "=r"(bf[2 * jp + 1][1])
                : "r"(bd));
        }
#pragma unroll
        for (int im = 0; im < 4; im++)
#pragma unroll
            for (int jn = 0; jn < 8; jn++) {
                asm volatile(
                    "mma.sync.aligned.m16n8k8.row.col.f32.tf32.tf32.f32 "
                    "{%0,%1,%2,%3}, {%4,%5,%6,%7}, {%8,%9}, {%0,%1,%2,%3};\n"
                    : "+f"(acc[im][jn][0]), "+f"(acc[im][jn][1]),
                      "+f"(acc[im][jn][2]), "+f"(acc[im][jn][3])
                    : "r"(af[im][0]), "r"(af[im][1]),
                      "r"(af[im][2]), "r"(af[im][3]),
                      "r"(bf[jn][0]), "r"(bf[jn][1]));
            }
    };

    // prologue
    ldgA(0); ldgB(0, 0);
    stsA(0); stsB(0, 0);
    ldgB(0, 1);
    stsB(0, 1);
    __syncthreads();

    int buf = 0;
    for (int kt = 0; kt < ktiles; kt++) {
        const bool nxt = (kt + 1 < ktiles);
        if (nxt) { ldgA(kt + 1); ldgB(kt + 1, 0); }
        compute_ks(buf, 0);
        compute_ks(buf, 1);
        if (nxt) { stsB(buf ^ 1, 0); ldgB(kt + 1, 1); }
        compute_ks(buf, 2);
        compute_ks(buf, 3);
        if (nxt) {
            stsA(buf ^ 1); stsB(buf ^ 1, 1);
            __syncthreads();
        }
        buf ^= 1;
    }

    // epilogue
#pragma unroll
    for (int im = 0; im < 4; im++) {
        int r0 = bm * 128 + wm * 64 + im * 16 + lr;
#pragma unroll
        for (int jn = 0; jn < 8; jn++) {
            int cg = bn * 128 + wn * 64 + jn * 8 + lc * 2;
            float bv0 = 0.f, bv1 = 0.f;
            if (bias) { bv0 = bias[cg]; bv1 = bias[cg + 1]; }
            if (r0 < E_NUM) {
                float2 v; v.x = acc[im][jn][0] + bv0; v.y = acc[im][jn][1] + bv1;
                *reinterpret_cast<float2*>(C + (size_t)r0 * LDX + cg) = v;
            }
            if (r0 + 8 < E_NUM) {
                float2 v; v.x = acc[im][jn][2] + bv0; v.y = acc[im][jn][3] + bv1;
                *reinterpret_cast<float2*>(C + (size_t)(r0 + 8) * LDX + cg) = v;
            }
        }
    }
}

// ---------------- launch ----------------

extern "C" void kernel_launch(void* const* d_in, const int* in_sizes, int n_in,
                              void* d_out, int out_size)
{
    const float* x  = (const float*)d_in[0];
    // d_in[1] = x_edge: unused by the reference
    const float* w0 = (const float*)d_in[2];
    const float* b0 = (const float*)d_in[3];
    const float* w1 = (const float*)d_in[4];
    const float* w2 = (const float*)d_in[5];
    float* out = (float*)d_out;

    prep_w0t_k<<<(896 * 896 + 255) / 256, 256>>>(w0);
    prep_so2t_k<<<(1536 * 1536 + 255) / 256, 256>>>(w1, 768, 1);
    prep_so2t_k<<<(1280 * 1280 + 255) / 256, 256>>>(w2, 640, 2);

    float *pw0, *pw1, *pw2;
    cudaGetSymbolAddress((void**)&pw0, g_w0t);
    cudaGetSymbolAddress((void**)&pw1, g_w1t);
    cudaGetSymbolAddress((void**)&pw2, g_w2t);

    cudaFuncSetAttribute(gemm_tf32_k,
                         cudaFuncAttributeMaxDynamicSharedMemorySize, SMEM_BYTES);

    const int mb = (E_NUM + 127) / 128;   // 469
    // m=0: (E,896) @ (896,896) + bias  -> out cols 0..895
    gemm_tf32_k<<<dim3(7, mb), 128, SMEM_BYTES>>>(x,        pw0, b0,      out,        896,  896);
    // m=1: (E,1536) @ (1536,1536)      -> out cols 896..2431
    gemm_tf32_k<<<dim3(12, mb), 128, SMEM_BYTES>>>(x + 896,  pw1, nullptr, out + 896,  1536, 1536);
    // m=2: (E,1280) @ (1280,1280)      -> out cols 2432..3711
    gemm_tf32_k<<<dim3(10, mb), 128, SMEM_BYTES>>>(x + 2432, pw2, nullptr, out + 2432, 1280, 1280);
}